// round 16
// baseline (speedup 1.0000x reference)
#include <cuda_runtime.h>
#include <math.h>

// Problem dims (fixed by the reference)
#define Bv 32
#define Tv 128
#define Fv 64
#define Hv 64
#define BST 36           // state row stride [j][b]: conflict-free STS.128 (36 % 32 == 4)
#define WST 68           // transposed weight row stride [j][k]: conflict-free LDS.128
#define NTHREADS 256
#define STB (Hv*BST)     // one state plane: 2304 floats

typedef unsigned long long u64;

// ---------------------------------------------------------------------------
// Scratch (allocation-free): transposed inputs + precomputed time terms
// ---------------------------------------------------------------------------
__device__ float g_xT[Tv*Fv*Bv];   // x   -> [t][f][b]
__device__ float g_lT[Tv*Fv*Bv];   // l   -> [t][f][b]
__device__ float g_Tm[Tv*Fv*Bv];   // 1/log(t+e)
__device__ float g_sTm[Tv*Fv*Bv];  // sigmoid(Tm)
__device__ float g_fw[Tv*Bv];      // sum_f exp(-0.5*freq[b,t,f])

struct KParams { const float* p[30]; };

// ---------------------------------------------------------------------------
// Prologue: transpose + time precompute + cross-feature freq reduction
// ---------------------------------------------------------------------------
__global__ void prologue_kernel(KParams prm) {
    int b  = blockIdx.x >> 7;          // / Tv
    int t  = blockIdx.x & (Tv - 1);
    int fi = threadIdx.x;

    const float* inputs = prm.p[0];
    const float* times  = prm.p[1];
    const float* lastv  = prm.p[2];
    const float* freqs  = prm.p[3];

    int gin  = (b*Tv + t)*Fv + fi;     // [B,T,F]
    int gout = (t*Fv + fi)*Bv + b;     // [T,F,B]

    g_xT[gout] = inputs[gin];
    g_lT[gout] = lastv[gin];
    float tv = times[gin];
    float tm = 1.0f / logf(tv + 2.718281828459045f);
    g_Tm[gout]  = tm;
    g_sTm[gout] = 1.0f / (1.0f + expf(-tm));

    float e = expf(-0.5f * freqs[gin]);
    #pragma unroll
    for (int off = 16; off > 0; off >>= 1)
        e += __shfl_down_sync(0xffffffffu, e, off);
    __shared__ float red[2];
    if ((threadIdx.x & 31) == 0) red[threadIdx.x >> 5] = e;
    __syncthreads();
    if (threadIdx.x == 0) g_fw[t*Bv + b] = red[0] + red[1];
}

// ---------------------------------------------------------------------------
// Packed f32x2 helpers
// ---------------------------------------------------------------------------
__device__ __forceinline__ u64 pk2(float x) {
    u64 r; asm("mov.b64 %0, {%1, %1};" : "=l"(r) : "f"(x)); return r;
}
__device__ __forceinline__ void fma2(u64& d, u64 a, u64 b) {
    asm("fma.rn.f32x2 %0, %1, %2, %0;" : "+l"(d) : "l"(a), "l"(b));
}
__device__ __forceinline__ float2 up2(u64 v) {
    float2 r; asm("mov.b64 {%0, %1}, %2;" : "=f"(r.x), "=f"(r.y) : "l"(v)); return r;
}

// ---------------------------------------------------------------------------
// Fast-but-accurate activations (identical numerics to all prior rounds)
// ---------------------------------------------------------------------------
__device__ __forceinline__ float sigf(float x) {
    return __fdividef(1.0f, 1.0f + __expf(-x));
}
__device__ __forceinline__ float tanf_(float x) {
    float e = __expf(-2.0f * fabsf(x));
    float r = __fdividef(1.0f - e, 1.0f + e);
    return copysignf(r, x);
}
__device__ __forceinline__ float eluf(float x) {
    return x > 0.0f ? x : (__expf(x) - 1.0f);
}

// ---------------------------------------------------------------------------
// Main kernel: one CTA per (feature, direction), 256 threads (8 warps).
// R16 warp re-index vs R15 (arithmetic 100% identical, pure renaming):
//   warp w: jq = w&3 (16 columns), bg = w>>2 (16 batches, base bg*16)
//   lane:   bh = lane>>4, jidx = lane&15; jcol = jq*16 + jidx
//   thread owns jcol for 8 batches bsel = bg*16 + bh*8.
// Weight redundancy drops 4x -> 2x, and each weight LDS.128 has only 16
// distinct lane addresses (upper half-warp broadcasts) -> ~2 wavefronts.
// Coupling widens to 4-warp groups: bar.sync(bg+1, 128). SMSP hosts warps
// of both bgroups (w, w+4) -> phase drift retained.
// ---------------------------------------------------------------------------
#define SMEM_FLOATS (7*Hv*WST + 6*STB)   // 30464 + 13824 = 44288 floats = 173 KB

__global__ __launch_bounds__(NTHREADS)
void tlstm_kernel(KParams prm, float* __restrict__ out) {
    const int f    = blockIdx.x;
    const int dir  = blockIdx.y;
    const int tid  = threadIdx.x;
    const int w    = tid >> 5;
    const int lane = tid & 31;
    const int jq   = w & 3;
    const int bg   = w >> 2;
    const int bh   = lane >> 4;
    const int jidx = lane & 15;
    const int jcol = jq * 16 + jidx;
    const int bsel = bg * 16 + bh * 8;   // this thread's 8-batch base
    const int barid = bg + 1;            // named barrier per 4-warp bgroup

    extern __shared__ float sm[];
    float* wT = sm;                    // [7][Hv*WST] : wT[m][j*WST + k]
    float* sB = sm + 7*Hv*WST;         // [2 parities][h | c | h2], each Hv*BST

    // ---- transpose per-feature weights into smem ----
    #pragma unroll
    for (int m = 0; m < 7; m++) {
        const float* gw = prm.p[12 + m] + (size_t)f * (Hv*Hv);
        float* wm = wT + m*Hv*WST;
        for (int i = tid; i < Hv*Hv; i += NTHREADS) {
            int k = i >> 6, j = i & 63;
            wm[j*WST + k] = gw[i];
        }
    }
    // zero h and c of buffer 0
    for (int i = tid; i < 2*STB; i += NTHREADS) sB[i] = 0.0f;

    // ---- hoist per-column params (loop-invariant) into registers ----
    const float Uj  = prm.p[4 ][f*Hv + jcol];
    const float Ui  = prm.p[5 ][f*Hv + jcol];
    const float Uf  = prm.p[6 ][f*Hv + jcol];
    const float Uo  = prm.p[7 ][f*Hv + jcol];
    const float Uc  = prm.p[8 ][f*Hv + jcol];
    const float Ul  = prm.p[9 ][f*Hv + jcol];
    const float Ut  = prm.p[10][f*Hv + jcol];
    const float Dw  = prm.p[11][f*Hv + jcol];
    const float Wci = prm.p[19][f*Hv + jcol];
    const float Wcf = prm.p[20][f*Hv + jcol];
    const float Wco = prm.p[21][f*Hv + jcol];
    const float bj  = prm.p[22][f*Hv + jcol];
    const float bi  = prm.p[23][f*Hv + jcol];
    const float bf  = prm.p[24][f*Hv + jcol];
    const float bo  = prm.p[25][f*Hv + jcol];
    const float bc  = prm.p[26][f*Hv + jcol];
    const float bl  = prm.p[27][f*Hv + jcol];
    const float bt  = prm.p[28][f*Hv + jcol];
    const float bd  = prm.p[29][f*Hv + jcol];

    // ---- initial lt[0] and h2[0] = 0 + lt[0] into buffer 0 ----
    float ltr[8];
    {
        const float4 lA = *(const float4*)&g_lT[(0*Fv + f)*Bv + bsel];
        const float4 lB = *(const float4*)&g_lT[(0*Fv + f)*Bv + bsel + 4];
        const float lva[8] = {lA.x,lA.y,lA.z,lA.w, lB.x,lB.y,lB.z,lB.w};
        #pragma unroll
        for (int bb = 0; bb < 8; bb++) ltr[bb] = eluf(lva[bb]*Ul + bl);
        *(float4*)(sB + 2*STB + jcol*BST + bsel)     = make_float4(ltr[0],ltr[1],ltr[2],ltr[3]);
        *(float4*)(sB + 2*STB + jcol*BST + bsel + 4) = make_float4(ltr[4],ltr[5],ltr[6],ltr[7]);
    }
    __syncthreads();

    float creg[8] = {0.f,0.f,0.f,0.f,0.f,0.f,0.f,0.f};

    const float* wDd  = wT + 5*Hv*WST + jcol*WST;   // W_d row for this column
    const float* wDec = wT + 6*Hv*WST + jcol*WST;   // W_decomp row

    for (int s = 0; s < Tv; s++) {
        const int p  = s & 1;
        const int np = p ^ 1;
        const float* cH  = sB + p*3*STB;
        const float* cC  = cH + STB;
        const float* cH2 = cC + STB;
        float* nH  = sB + np*3*STB;
        float* nC  = nH + STB;
        float* nH2 = nC + STB;

        const int t_x   = dir ? (Tv-1-s) : s;
        const int t_tm  = dir ? (s == 0 ? 0 : Tv - s) : s;
        const int t_out = dir ? (Tv-1-s) : s;
        const int lidx  = (s + 1 < Tv) ? s + 1 : Tv - 1;   // l for NEXT step

        // ===== hoisted gmem loads (latency covered by the fused matmul) =====
        const float4 tmA = *(const float4*)&g_Tm [(t_tm*Fv + f)*Bv + bsel];
        const float4 tmB = *(const float4*)&g_Tm [(t_tm*Fv + f)*Bv + bsel + 4];
        const float4 fwA = *(const float4*)&g_fw [ s*Bv + bsel];
        const float4 fwB = *(const float4*)&g_fw [ s*Bv + bsel + 4];
        const float4 xvA = *(const float4*)&g_xT [(t_x *Fv + f)*Bv + bsel];
        const float4 xvB = *(const float4*)&g_xT [(t_x *Fv + f)*Bv + bsel + 4];
        const float4 stA = *(const float4*)&g_sTm[(t_tm*Fv + f)*Bv + bsel];
        const float4 stB = *(const float4*)&g_sTm[(t_tm*Fv + f)*Bv + bsel + 4];
        const float4 lnA = *(const float4*)&g_lT [(lidx*Fv + f)*Bv + bsel];
        const float4 lnB = *(const float4*)&g_lT [(lidx*Fv + f)*Bv + bsel + 4];

        // ===== fused matmul: c@W_decomp, h@W_d, h2@{W_j,W_i,W_f,W_o,W_c,W_d}
        u64 aD[4] = {0ULL,0ULL,0ULL,0ULL};
        u64 aF[4] = {0ULL,0ULL,0ULL,0ULL};
        u64 acc[6][4];
        #pragma unroll
        for (int m = 0; m < 6; m++)
            #pragma unroll
            for (int q = 0; q < 4; q++) acc[m][q] = 0ULL;

        #pragma unroll 4
        for (int k0 = 0; k0 < Hv; k0 += 4) {
            float4 wv[6];
            #pragma unroll
            for (int m = 0; m < 6; m++)
                wv[m] = *(const float4*)(wT + m*Hv*WST + jcol*WST + k0);
            float4 wde = *(const float4*)(wDec + k0);
            float4 wdd = *(const float4*)(wDd  + k0);
            #pragma unroll
            for (int kk = 0; kk < 4; kk++) {
                int k = k0 + kk;
                ulonglong2 cu0 = *(const ulonglong2*)(cC  + k*BST + bsel);
                ulonglong2 cu1 = *(const ulonglong2*)(cC  + k*BST + bsel + 4);
                ulonglong2 hu0 = *(const ulonglong2*)(cH  + k*BST + bsel);
                ulonglong2 hu1 = *(const ulonglong2*)(cH  + k*BST + bsel + 4);
                ulonglong2 au0 = *(const ulonglong2*)(cH2 + k*BST + bsel);
                ulonglong2 au1 = *(const ulonglong2*)(cH2 + k*BST + bsel + 4);
                u64 we2 = pk2(((const float*)&wde)[kk]);
                u64 wd2 = pk2(((const float*)&wdd)[kk]);
                fma2(aD[0], cu0.x, we2); fma2(aD[1], cu0.y, we2);
                fma2(aD[2], cu1.x, we2); fma2(aD[3], cu1.y, we2);
                fma2(aF[0], hu0.x, wd2); fma2(aF[1], hu0.y, wd2);
                fma2(aF[2], hu1.x, wd2); fma2(aF[3], hu1.y, wd2);
                #pragma unroll
                for (int m = 0; m < 6; m++) {
                    u64 w2 = pk2(((const float*)&wv[m])[kk]);
                    fma2(acc[m][0], au0.x, w2);
                    fma2(acc[m][1], au0.y, w2);
                    fma2(acc[m][2], au1.x, w2);
                    fma2(acc[m][3], au1.y, w2);
                }
            }
        }

        // ===== elementwise (phase-1 + phase-2 fused, formulas unchanged) ====
        {
            float tma[8], fwa[8];
            tma[0]=tmA.x; tma[1]=tmA.y; tma[2]=tmA.z; tma[3]=tmA.w;
            tma[4]=tmB.x; tma[5]=tmB.y; tma[6]=tmB.z; tma[7]=tmB.w;
            fwa[0]=fwA.x; fwa[1]=fwA.y; fwa[2]=fwA.z; fwa[3]=fwA.w;
            fwa[4]=fwB.x; fwa[5]=fwB.y; fwa[6]=fwB.z; fwa[7]=fwB.w;
            float a1a[8], a2a[8];
            #pragma unroll
            for (int q = 0; q < 4; q++) {
                float2 d = up2(aD[q]); a1a[2*q] = d.x; a1a[2*q+1] = d.y;
                float2 g = up2(aF[q]); a2a[2*q] = g.x; a2a[2*q+1] = g.y;
            }
            float c2r[8];
            #pragma unroll
            for (int bb = 0; bb < 8; bb++) {
                float dst  = tanf_(a1a[bb]);
                float fd1  = sigf(fwa[bb]*Dw + a2a[bb] + bd);
                float ddec = dst * (tma[bb] * fd1);
                c2r[bb] = ddec + (creg[bb] - dst + ddec);
            }

            const float xva[8] = {xvA.x,xvA.y,xvA.z,xvA.w, xvB.x,xvB.y,xvB.z,xvB.w};
            const float sta[8] = {stA.x,stA.y,stA.z,stA.w, stB.x,stB.y,stB.z,stB.w};
            const float lna[8] = {lnA.x,lnA.y,lnA.z,lnA.w, lnB.x,lnB.y,lnB.z,lnB.w};
            float am[6][8];
            #pragma unroll
            for (int m = 0; m < 6; m++)
                #pragma unroll
                for (int q = 0; q < 4; q++) {
                    float2 v = up2(acc[m][q]);
                    am[m][2*q] = v.x; am[m][2*q+1] = v.y;
                }
            float hna[8], ltn[8];
            #pragma unroll
            for (int bb = 0; bb < 8; bb++) {
                float c2 = c2r[bb];
                float lt = ltr[bb];
                float jg  = tanf_(am[0][bb] + xva[bb]*Uj + bj);
                float tg  = sigf(xva[bb]*Ut + sta[bb] + bt);
                float fd2 = sigf(fwa[bb]*Dw + am[5][bb] + bd);
                float ig  = sigf(xva[bb]*Ui + am[1][bb] + c2*Wci + bi*fd2);
                float fg  = sigf(xva[bb]*Uf + am[2][bb] + c2*Wcf + bf + jg);
                float fn  = fg*tma[bb] + (1.0f - fg)*fd2;
                float cg  = tanf_(xva[bb]*Uc + am[4][bb] + bc);
                float ct  = (fn + tg)*c2 + ig*jg*tg*cg;
                float og  = sigf(xva[bb]*Uo + am[3][bb] + tg + lt + ct*Wco + bo);
                float hn  = og * tanf_(ct + lt);
                creg[bb] = ct;
                hna[bb]  = hn;
                ltn[bb]  = eluf(lna[bb]*Ul + bl);     // lt for step s+1
                out[((size_t)(t_out*Bv + bsel + bb)*Fv + f)*(2*Hv) + dir*Hv + jcol] = hn;
            }
            // store next-step state: h, c, h2 = h + lt[s+1]
            *(float4*)(nH  + jcol*BST + bsel)     = make_float4(hna[0],hna[1],hna[2],hna[3]);
            *(float4*)(nH  + jcol*BST + bsel + 4) = make_float4(hna[4],hna[5],hna[6],hna[7]);
            *(float4*)(nC  + jcol*BST + bsel)     = make_float4(creg[0],creg[1],creg[2],creg[3]);
            *(float4*)(nC  + jcol*BST + bsel + 4) = make_float4(creg[4],creg[5],creg[6],creg[7]);
            *(float4*)(nH2 + jcol*BST + bsel)     = make_float4(hna[0]+ltn[0],hna[1]+ltn[1],
                                                                hna[2]+ltn[2],hna[3]+ltn[3]);
            *(float4*)(nH2 + jcol*BST + bsel + 4) = make_float4(hna[4]+ltn[4],hna[5]+ltn[5],
                                                                hna[6]+ltn[6],hna[7]+ltn[7]);
            #pragma unroll
            for (int bb = 0; bb < 8; bb++) ltr[bb] = ltn[bb];
        }
        // named barrier over this bgroup's 4 warps (128 threads)
        asm volatile("bar.sync %0, %1;" :: "r"(barid), "r"(128) : "memory");
    }
}

// ---------------------------------------------------------------------------
// Launch
// ---------------------------------------------------------------------------
extern "C" void kernel_launch(void* const* d_in, const int* in_sizes, int n_in,
                              void* d_out, int out_size) {
    KParams prm;
    for (int i = 0; i < 30; i++) prm.p[i] = (const float*)d_in[i];

    cudaFuncSetAttribute(tlstm_kernel,
                         cudaFuncAttributeMaxDynamicSharedMemorySize,
                         SMEM_FLOATS * (int)sizeof(float));

    prologue_kernel<<<Bv*Tv, Fv>>>(prm);
    tlstm_kernel<<<dim3(Fv, 2), NTHREADS, SMEM_FLOATS * sizeof(float)>>>(
        prm, (float*)d_out);
}